// round 1
// baseline (speedup 1.0000x reference)
#include <cuda_runtime.h>
#include <cuda_bf16.h>
#include <math.h>

// Problem dims
#define NB   1024
#define LL   128
#define HH   512
#define OO   32000
#define H2   1024   // 2H
#define H3   1536   // 3H

// ---------------- scratch (device globals; no allocation allowed) -----------
__device__ float g_cat[NB * H2];    // [embedded | hidden], later [embedded | attn_applied]
__device__ float g_x  [NB * HH];    // relu(comb)
__device__ float g_gx [NB * H3];
__device__ float g_gh [NB * H3];

// ---------------- K1: build cat = [emb[id] | hidden] ------------------------
__global__ void k_build_cat(const int* __restrict__ ids,
                            const float* __restrict__ hidden,
                            const float* __restrict__ emb)
{
    int n = blockIdx.x;
    int id = ids[n];
    const float* e = emb + (size_t)id * HH;
    const float* h = hidden + (size_t)n * HH;
    float* c = g_cat + (size_t)n * H2;
    for (int i = threadIdx.x; i < HH; i += blockDim.x) {
        c[i]       = e[i];
        c[HH + i]  = h[i];
    }
}

// ---------------- generic tiled SGEMM:  C[M,Nd] = A[M,K] * W[Nd,K]^T + bias --
template<int BM, int BN, int BK, int TM, int TN>
__global__ void k_gemm_nt(const float* __restrict__ A,
                          const float* __restrict__ W,
                          const float* __restrict__ bias,
                          float* __restrict__ C,
                          int M, int Nd, int K, int relu)
{
    constexpr int THREADS = (BM / TM) * (BN / TN);
    __shared__ float As[BK][BM + 4];
    __shared__ float Ws[BK][BN + 4];

    int bm = blockIdx.y * BM;
    int bn = blockIdx.x * BN;
    int tid = threadIdx.x;
    int tx = tid % (BN / TN);
    int ty = tid / (BN / TN);

    float acc[TM][TN];
    #pragma unroll
    for (int i = 0; i < TM; i++)
        #pragma unroll
        for (int j = 0; j < TN; j++) acc[i][j] = 0.f;

    for (int k0 = 0; k0 < K; k0 += BK) {
        #pragma unroll
        for (int idx = tid; idx < BM * BK; idx += THREADS) {
            int m = idx / BK, k = idx % BK;
            As[k][m] = A[(size_t)(bm + m) * K + k0 + k];
        }
        #pragma unroll
        for (int idx = tid; idx < BN * BK; idx += THREADS) {
            int n = idx / BK, k = idx % BK;
            Ws[k][n] = W[(size_t)(bn + n) * K + k0 + k];
        }
        __syncthreads();

        #pragma unroll
        for (int kk = 0; kk < BK; kk++) {
            float rm[TM], rn[TN];
            #pragma unroll
            for (int i = 0; i < TM; i++) rm[i] = As[kk][ty * TM + i];
            #pragma unroll
            for (int j = 0; j < TN; j++) rn[j] = Ws[kk][tx * TN + j];
            #pragma unroll
            for (int i = 0; i < TM; i++)
                #pragma unroll
                for (int j = 0; j < TN; j++)
                    acc[i][j] = fmaf(rm[i], rn[j], acc[i][j]);
        }
        __syncthreads();
    }

    #pragma unroll
    for (int i = 0; i < TM; i++) {
        int m = bm + ty * TM + i;
        #pragma unroll
        for (int j = 0; j < TN; j++) {
            int n = bn + tx * TN + j;
            float v = acc[i][j] + bias[n];
            if (relu) v = v > 0.f ? v : 0.f;
            C[(size_t)m * Nd + n] = v;
        }
    }
}

// ---------------- K3: softmax over L=128 (in place) -------------------------
__global__ void k_softmax128(float* __restrict__ x)
{
    __shared__ float red[128];
    int n = blockIdx.x;
    int t = threadIdx.x;
    float* row = x + (size_t)n * LL;
    float v = row[t];

    red[t] = v; __syncthreads();
    for (int s = 64; s > 0; s >>= 1) {
        if (t < s) red[t] = fmaxf(red[t], red[t + s]);
        __syncthreads();
    }
    float m = red[0]; __syncthreads();

    float e = expf(v - m);
    red[t] = e; __syncthreads();
    for (int s = 64; s > 0; s >>= 1) {
        if (t < s) red[t] += red[t + s];
        __syncthreads();
    }
    float sum = red[0];
    row[t] = e / sum;
}

// ---------------- K4: attn_applied = einsum (with fused mask) ---------------
// writes into the second half of g_cat ( => cat2 = [embedded | attn_applied] )
__global__ void k_attn_apply(const float* __restrict__ eo,
                             const float* __restrict__ mask,
                             const float* __restrict__ w)
{
    __shared__ float ws[LL];
    int n = blockIdx.x;
    int h = threadIdx.x;              // 512 threads
    if (h < LL) ws[h] = w[(size_t)n * LL + h];
    __syncthreads();

    const float* e  = eo   + (size_t)n * LL * HH + h;
    const float* mk = mask + (size_t)n * LL * HH + h;
    float acc = 0.f;
    #pragma unroll 8
    for (int l = 0; l < LL; l++)
        acc = fmaf(ws[l], e[(size_t)l * HH] * mk[(size_t)l * HH], acc);

    g_cat[(size_t)n * H2 + HH + h] = acc;
}

// ---------------- K8: GRU gate pointwise -------------------------------------
__global__ void k_gru(const float* __restrict__ hidden,
                      float* __restrict__ h_new)
{
    int idx = blockIdx.x * blockDim.x + threadIdx.x;
    if (idx >= NB * HH) return;
    int n = idx >> 9;          // /512
    int h = idx & (HH - 1);
    size_t base = (size_t)n * H3 + h;

    float xr = g_gx[base], xz = g_gx[base + HH], xn = g_gx[base + 2 * HH];
    float hr = g_gh[base], hz = g_gh[base + HH], hn = g_gh[base + 2 * HH];

    float r = 1.f / (1.f + expf(-(xr + hr)));
    float z = 1.f / (1.f + expf(-(xz + hz)));
    float nn = tanhf(xn + r * hn);
    float hv = hidden[idx];
    h_new[idx] = (1.f - z) * nn + z * hv;
}

// ---------------- K10: log_softmax over O=32000 (in place) ------------------
__global__ void k_log_softmax(float* __restrict__ x)
{
    __shared__ float red[256];
    int n = blockIdx.x;
    int t = threadIdx.x;
    float* row = x + (size_t)n * OO;

    // pass 1: max
    float m = -INFINITY;
    for (int i = t; i < OO; i += 256) m = fmaxf(m, row[i]);
    red[t] = m; __syncthreads();
    for (int s = 128; s > 0; s >>= 1) {
        if (t < s) red[t] = fmaxf(red[t], red[t + s]);
        __syncthreads();
    }
    float M = red[0]; __syncthreads();

    // pass 2: sum(exp)
    float s = 0.f;
    for (int i = t; i < OO; i += 256) s += expf(row[i] - M);
    red[t] = s; __syncthreads();
    for (int st = 128; st > 0; st >>= 1) {
        if (t < st) red[t] += red[t + st];
        __syncthreads();
    }
    float lse = M + logf(red[0]);

    // pass 3: write
    for (int i = t; i < OO; i += 256) row[i] -= lse;
}

// ---------------- launch ------------------------------------------------------
extern "C" void kernel_launch(void* const* d_in, const int* in_sizes, int n_in,
                              void* d_out, int out_size)
{
    const int*   ids     = (const int*)  d_in[0];
    const float* hidden  = (const float*)d_in[1];
    const float* eo      = (const float*)d_in[2];
    const float* mask    = (const float*)d_in[3];
    const float* emb     = (const float*)d_in[4];
    const float* attn_W  = (const float*)d_in[5];
    const float* attn_b  = (const float*)d_in[6];
    const float* comb_W  = (const float*)d_in[7];
    const float* comb_b  = (const float*)d_in[8];
    const float* W_ih    = (const float*)d_in[9];
    const float* W_hh    = (const float*)d_in[10];
    const float* b_ih    = (const float*)d_in[11];
    const float* b_hh    = (const float*)d_in[12];
    const float* out_W   = (const float*)d_in[13];
    const float* out_b   = (const float*)d_in[14];

    float* out    = (float*)d_out;                       // [N, O]   log-probs
    float* h_new  = out + (size_t)NB * OO;               // [N, H]
    float* attn_w = h_new + (size_t)NB * HH;             // [N, L]

    float* catp;  cudaGetSymbolAddress((void**)&catp, g_cat);
    float* xp;    cudaGetSymbolAddress((void**)&xp,   g_x);
    float* gxp;   cudaGetSymbolAddress((void**)&gxp,  g_gx);
    float* ghp;   cudaGetSymbolAddress((void**)&ghp,  g_gh);

    // 1. cat = [emb[ids] | hidden]
    k_build_cat<<<NB, 256>>>(ids, hidden, emb);

    // 2. attn logits -> attn_w region, + bias
    {
        dim3 grid(LL / 64, NB / 64);
        k_gemm_nt<64, 64, 16, 4, 4><<<grid, 256>>>(catp, attn_W, attn_b,
                                                   attn_w, NB, LL, H2, 0);
    }
    // 3. softmax over L
    k_softmax128<<<NB, 128>>>(attn_w);

    // 4. attn_applied (fused mask) -> second half of cat
    k_attn_apply<<<NB, HH>>>(eo, mask, attn_w);

    // 5. x = relu(cat2 @ comb_W^T + b)
    {
        dim3 grid(HH / 64, NB / 64);
        k_gemm_nt<64, 64, 16, 4, 4><<<grid, 256>>>(catp, comb_W, comb_b,
                                                   xp, NB, HH, H2, 1);
    }
    // 6. gx = x @ W_ih^T + b_ih ; 7. gh = hidden @ W_hh^T + b_hh
    {
        dim3 grid(H3 / 64, NB / 64);
        k_gemm_nt<64, 64, 16, 4, 4><<<grid, 256>>>(xp, W_ih, b_ih,
                                                   gxp, NB, H3, HH, 0);
        k_gemm_nt<64, 64, 16, 4, 4><<<grid, 256>>>(hidden, W_hh, b_hh,
                                                   ghp, NB, H3, HH, 0);
    }
    // 8. GRU gates -> h_new output region
    k_gru<<<(NB * HH + 255) / 256, 256>>>(hidden, h_new);

    // 9. logits = h_new @ out_W^T + out_b  (the big one)
    {
        dim3 grid(OO / 128, NB / 128);
        k_gemm_nt<128, 128, 16, 8, 8><<<grid, 256>>>(h_new, out_W, out_b,
                                                     out, NB, OO, HH, 0);
    }
    // 10. log-softmax in place
    k_log_softmax<<<NB, 256>>>(out);
}

// round 2
// speedup vs baseline: 3.2793x; 3.2793x over previous
#include <cuda_runtime.h>
#include <cuda_bf16.h>
#include <math.h>
#include <stdint.h>

// Problem dims
#define NB   1024
#define LL   128
#define HH   512
#define OO   32000
#define H2   1024   // 2H
#define H3   1536   // 3H

#define PAD 36      // smem row stride in floats (32 data + 4 pad) -> conflict-free frag loads

// ---------------- scratch (device globals; no allocation allowed) -----------
__device__ float g_cat[NB * H2];    // [embedded | hidden], later [embedded | attn_applied]
__device__ float g_x  [NB * HH];    // relu(comb)
__device__ float g_gx [NB * H3];
__device__ float g_gh [NB * H3];

// ---------------- helpers ----------------------------------------------------
__device__ __forceinline__ void cpasync16(void* s, const void* g)
{
    uint32_t sa = (uint32_t)__cvta_generic_to_shared(s);
    asm volatile("cp.async.cg.shared.global [%0], [%1], 16;\n" :: "r"(sa), "l"(g));
}
__device__ __forceinline__ void cp_commit() { asm volatile("cp.async.commit_group;\n"); }
__device__ __forceinline__ void cp_wait1()  { asm volatile("cp.async.wait_group 1;\n"); }

__device__ __forceinline__ void mma_tf32(float* d, const uint32_t* a, const uint32_t* b)
{
    asm volatile(
        "mma.sync.aligned.m16n8k8.row.col.f32.tf32.tf32.f32 "
        "{%0,%1,%2,%3}, {%4,%5,%6,%7}, {%8,%9}, {%0,%1,%2,%3};\n"
        : "+f"(d[0]), "+f"(d[1]), "+f"(d[2]), "+f"(d[3])
        : "r"(a[0]), "r"(a[1]), "r"(a[2]), "r"(a[3]), "r"(b[0]), "r"(b[1]));
}

// ---------------- tf32 tensor-core GEMM: C[M,Nd] = A[M,K] @ W[Nd,K]^T + bias --
// BM=BN=128, BK=32, 256 threads (8 warps, 2x4), warp tile 64x32.
// Requires M%128==0, Nd%128==0, K%32==0.
__global__ __launch_bounds__(256, 2)
void k_gemm_tf32(const float* __restrict__ A, const float* __restrict__ W,
                 const float* __restrict__ bias, float* __restrict__ C,
                 int M, int Nd, int K, int relu)
{
    extern __shared__ float sm[];
    float* As = sm;                      // [2][128][PAD]
    float* Bs = sm + 2 * 128 * PAD;      // [2][128][PAD]

    const int bm   = blockIdx.y * 128;
    const int bn   = blockIdx.x * 128;
    const int tid  = threadIdx.x;
    const int warp = tid >> 5;
    const int lane = tid & 31;
    const int gid  = lane >> 2;          // 0..7
    const int tig  = lane & 3;           // 0..3
    const int wm   = (warp >> 2) * 64;   // warp row offset in tile
    const int wn   = (warp & 3) * 32;    // warp col offset in tile

    float acc[4][4][4];
    #pragma unroll
    for (int i = 0; i < 4; i++)
        #pragma unroll
        for (int j = 0; j < 4; j++)
            #pragma unroll
            for (int r = 0; r < 4; r++) acc[i][j][r] = 0.f;

    const float* Ag = A + (size_t)bm * K;
    const float* Wg = W + (size_t)bn * K;

    const int nIter = K >> 5;            // K/32

    // async tile loader: 128 rows x 32 cols = 1024 float4; 4 per thread
    auto load_tiles = [&](int it, int buf) {
        const float* a_src = Ag + it * 32;
        const float* w_src = Wg + it * 32;
        float* a_dst = As + buf * 128 * PAD;
        float* w_dst = Bs + buf * 128 * PAD;
        #pragma unroll
        for (int i = 0; i < 4; i++) {
            int f = tid + i * 256;
            int r = f >> 3;
            int c = (f & 7) * 4;
            cpasync16(&a_dst[r * PAD + c], a_src + (size_t)r * K + c);
        }
        #pragma unroll
        for (int i = 0; i < 4; i++) {
            int f = tid + i * 256;
            int r = f >> 3;
            int c = (f & 7) * 4;
            cpasync16(&w_dst[r * PAD + c], w_src + (size_t)r * K + c);
        }
    };

    load_tiles(0, 0);
    cp_commit();

    int buf = 0;
    for (int it = 0; it < nIter; ++it) {
        if (it + 1 < nIter) load_tiles(it + 1, buf ^ 1);
        cp_commit();
        cp_wait1();
        __syncthreads();

        const float* a_s = As + buf * 128 * PAD;
        const float* b_s = Bs + buf * 128 * PAD;

        #pragma unroll
        for (int kk = 0; kk < 4; kk++) {
            uint32_t af[4][4], bf[4][2];
            #pragma unroll
            for (int mt = 0; mt < 4; mt++) {
                int m0 = wm + mt * 16 + gid;
                af[mt][0] = __float_as_uint(a_s[(m0    ) * PAD + kk * 8 + tig    ]);
                af[mt][1] = __float_as_uint(a_s[(m0 + 8) * PAD + kk * 8 + tig    ]);
                af[mt][2] = __float_as_uint(a_s[(m0    ) * PAD + kk * 8 + tig + 4]);
                af[mt][3] = __float_as_uint(a_s[(m0 + 8) * PAD + kk * 8 + tig + 4]);
            }
            #pragma unroll
            for (int nt = 0; nt < 4; nt++) {
                int n0 = wn + nt * 8 + gid;
                bf[nt][0] = __float_as_uint(b_s[n0 * PAD + kk * 8 + tig    ]);
                bf[nt][1] = __float_as_uint(b_s[n0 * PAD + kk * 8 + tig + 4]);
            }
            #pragma unroll
            for (int mt = 0; mt < 4; mt++)
                #pragma unroll
                for (int nt = 0; nt < 4; nt++)
                    mma_tf32(acc[mt][nt], af[mt], bf[nt]);
        }
        __syncthreads();
        buf ^= 1;
    }

    // epilogue: bias (+ optional relu), vectorized float2 stores
    #pragma unroll
    for (int mt = 0; mt < 4; mt++) {
        int r0 = bm + wm + mt * 16 + gid;
        #pragma unroll
        for (int nt = 0; nt < 4; nt++) {
            int c0 = bn + wn + nt * 8 + tig * 2;
            float b0v = bias[c0], b1v = bias[c0 + 1];
            float v0 = acc[mt][nt][0] + b0v;
            float v1 = acc[mt][nt][1] + b1v;
            float v2 = acc[mt][nt][2] + b0v;
            float v3 = acc[mt][nt][3] + b1v;
            if (relu) {
                v0 = fmaxf(v0, 0.f); v1 = fmaxf(v1, 0.f);
                v2 = fmaxf(v2, 0.f); v3 = fmaxf(v3, 0.f);
            }
            *(float2*)&C[(size_t)(r0    ) * Nd + c0] = make_float2(v0, v1);
            *(float2*)&C[(size_t)(r0 + 8) * Nd + c0] = make_float2(v2, v3);
        }
    }
}

// ---------------- K1: build cat = [emb[id] | hidden] ------------------------
__global__ void k_build_cat(const int* __restrict__ ids,
                            const float* __restrict__ hidden,
                            const float* __restrict__ emb)
{
    int n = blockIdx.x;
    int id = ids[n];
    const float* e = emb + (size_t)id * HH;
    const float* h = hidden + (size_t)n * HH;
    float* c = g_cat + (size_t)n * H2;
    for (int i = threadIdx.x; i < HH; i += blockDim.x) {
        c[i]      = e[i];
        c[HH + i] = h[i];
    }
}

// ---------------- fp32 fallback SGEMM (used only for the tiny attn GEMM) ----
template<int BM, int BN, int BK, int TM, int TN>
__global__ void k_gemm_nt(const float* __restrict__ A,
                          const float* __restrict__ W,
                          const float* __restrict__ bias,
                          float* __restrict__ C,
                          int M, int Nd, int K, int relu)
{
    constexpr int THREADS = (BM / TM) * (BN / TN);
    __shared__ float As[BK][BM + 4];
    __shared__ float Ws[BK][BN + 4];

    int bm = blockIdx.y * BM;
    int bn = blockIdx.x * BN;
    int tid = threadIdx.x;
    int tx = tid % (BN / TN);
    int ty = tid / (BN / TN);

    float acc[TM][TN];
    #pragma unroll
    for (int i = 0; i < TM; i++)
        #pragma unroll
        for (int j = 0; j < TN; j++) acc[i][j] = 0.f;

    for (int k0 = 0; k0 < K; k0 += BK) {
        #pragma unroll
        for (int idx = tid; idx < BM * BK; idx += THREADS) {
            int m = idx / BK, k = idx % BK;
            As[k][m] = A[(size_t)(bm + m) * K + k0 + k];
        }
        #pragma unroll
        for (int idx = tid; idx < BN * BK; idx += THREADS) {
            int n = idx / BK, k = idx % BK;
            Ws[k][n] = W[(size_t)(bn + n) * K + k0 + k];
        }
        __syncthreads();

        #pragma unroll
        for (int kk = 0; kk < BK; kk++) {
            float rm[TM], rn[TN];
            #pragma unroll
            for (int i = 0; i < TM; i++) rm[i] = As[kk][ty * TM + i];
            #pragma unroll
            for (int j = 0; j < TN; j++) rn[j] = Ws[kk][tx * TN + j];
            #pragma unroll
            for (int i = 0; i < TM; i++)
                #pragma unroll
                for (int j = 0; j < TN; j++)
                    acc[i][j] = fmaf(rm[i], rn[j], acc[i][j]);
        }
        __syncthreads();
    }

    #pragma unroll
    for (int i = 0; i < TM; i++) {
        int m = bm + ty * TM + i;
        #pragma unroll
        for (int j = 0; j < TN; j++) {
            int n = bn + tx * TN + j;
            float v = acc[i][j] + bias[n];
            if (relu) v = v > 0.f ? v : 0.f;
            C[(size_t)m * Nd + n] = v;
        }
    }
}

// ---------------- K3: softmax over L=128 (in place) -------------------------
__global__ void k_softmax128(float* __restrict__ x)
{
    __shared__ float red[128];
    int n = blockIdx.x;
    int t = threadIdx.x;
    float* row = x + (size_t)n * LL;
    float v = row[t];

    red[t] = v; __syncthreads();
    for (int s = 64; s > 0; s >>= 1) {
        if (t < s) red[t] = fmaxf(red[t], red[t + s]);
        __syncthreads();
    }
    float m = red[0]; __syncthreads();

    float e = expf(v - m);
    red[t] = e; __syncthreads();
    for (int s = 64; s > 0; s >>= 1) {
        if (t < s) red[t] += red[t + s];
        __syncthreads();
    }
    float sum = red[0];
    row[t] = e / sum;
}

// ---------------- K4: attn_applied = einsum (with fused mask) ---------------
__global__ void k_attn_apply(const float* __restrict__ eo,
                             const float* __restrict__ mask,
                             const float* __restrict__ w)
{
    __shared__ float ws[LL];
    int n = blockIdx.x;
    int h = threadIdx.x;              // 512 threads
    if (h < LL) ws[h] = w[(size_t)n * LL + h];
    __syncthreads();

    const float* e  = eo   + (size_t)n * LL * HH + h;
    const float* mk = mask + (size_t)n * LL * HH + h;
    float acc = 0.f;
    #pragma unroll 8
    for (int l = 0; l < LL; l++)
        acc = fmaf(ws[l], e[(size_t)l * HH] * mk[(size_t)l * HH], acc);

    g_cat[(size_t)n * H2 + HH + h] = acc;
}

// ---------------- K8: GRU gate pointwise -------------------------------------
__global__ void k_gru(const float* __restrict__ hidden,
                      float* __restrict__ h_new)
{
    int idx = blockIdx.x * blockDim.x + threadIdx.x;
    if (idx >= NB * HH) return;
    int n = idx >> 9;
    int h = idx & (HH - 1);
    size_t base = (size_t)n * H3 + h;

    float xr = g_gx[base], xz = g_gx[base + HH], xn = g_gx[base + 2 * HH];
    float hr = g_gh[base], hz = g_gh[base + HH], hn = g_gh[base + 2 * HH];

    float r = 1.f / (1.f + expf(-(xr + hr)));
    float z = 1.f / (1.f + expf(-(xz + hz)));
    float nn = tanhf(xn + r * hn);
    float hv = hidden[idx];
    h_new[idx] = (1.f - z) * nn + z * hv;
}

// ---------------- K10: log_softmax over O=32000 (in place) ------------------
__global__ void k_log_softmax(float* __restrict__ x)
{
    __shared__ float red[256];
    int n = blockIdx.x;
    int t = threadIdx.x;
    float* row = x + (size_t)n * OO;

    float m = -INFINITY;
    for (int i = t; i < OO; i += 256) m = fmaxf(m, row[i]);
    red[t] = m; __syncthreads();
    for (int s = 128; s > 0; s >>= 1) {
        if (t < s) red[t] = fmaxf(red[t], red[t + s]);
        __syncthreads();
    }
    float M = red[0]; __syncthreads();

    float s = 0.f;
    for (int i = t; i < OO; i += 256) s += expf(row[i] - M);
    red[t] = s; __syncthreads();
    for (int st = 128; st > 0; st >>= 1) {
        if (t < st) red[t] += red[t + st];
        __syncthreads();
    }
    float lse = M + logf(red[0]);

    for (int i = t; i < OO; i += 256) row[i] -= lse;
}

// ---------------- launch ------------------------------------------------------
extern "C" void kernel_launch(void* const* d_in, const int* in_sizes, int n_in,
                              void* d_out, int out_size)
{
    const int*   ids     = (const int*)  d_in[0];
    const float* hidden  = (const float*)d_in[1];
    const float* eo      = (const float*)d_in[2];
    const float* mask    = (const float*)d_in[3];
    const float* emb     = (const float*)d_in[4];
    const float* attn_W  = (const float*)d_in[5];
    const float* attn_b  = (const float*)d_in[6];
    const float* comb_W  = (const float*)d_in[7];
    const float* comb_b  = (const float*)d_in[8];
    const float* W_ih    = (const float*)d_in[9];
    const float* W_hh    = (const float*)d_in[10];
    const float* b_ih    = (const float*)d_in[11];
    const float* b_hh    = (const float*)d_in[12];
    const float* out_W   = (const float*)d_in[13];
    const float* out_b   = (const float*)d_in[14];

    float* out    = (float*)d_out;                       // [N, O]
    float* h_new  = out + (size_t)NB * OO;               // [N, H]
    float* attn_w = h_new + (size_t)NB * HH;             // [N, L]

    float* catp;  cudaGetSymbolAddress((void**)&catp, g_cat);
    float* xp;    cudaGetSymbolAddress((void**)&xp,   g_x);
    float* gxp;   cudaGetSymbolAddress((void**)&gxp,  g_gx);
    float* ghp;   cudaGetSymbolAddress((void**)&ghp,  g_gh);

    const int SMEM = 2 * 2 * 128 * PAD * sizeof(float);  // 73728 B
    cudaFuncSetAttribute(k_gemm_tf32, cudaFuncAttributeMaxDynamicSharedMemorySize, SMEM);

    // 1. cat = [emb[ids] | hidden]
    k_build_cat<<<NB, 256>>>(ids, hidden, emb);

    // 2. attn logits (small; fp32) -> attn_w, + bias
    {
        dim3 grid(LL / 64, NB / 64);
        k_gemm_nt<64, 64, 16, 4, 4><<<grid, 256>>>(catp, attn_W, attn_b,
                                                   attn_w, NB, LL, H2, 0);
    }
    // 3. softmax over L
    k_softmax128<<<NB, 128>>>(attn_w);

    // 4. attn_applied (fused mask) -> second half of cat
    k_attn_apply<<<NB, HH>>>(eo, mask, attn_w);

    // 5. x = relu(cat2 @ comb_W^T + b)  [tf32 tensor cores]
    {
        dim3 grid(HH / 128, NB / 128);
        k_gemm_tf32<<<grid, 256, SMEM>>>(catp, comb_W, comb_b, xp, NB, HH, H2, 1);
    }
    // 6/7. GRU input/hidden GEMMs  [tf32 tensor cores]
    {
        dim3 grid(H3 / 128, NB / 128);
        k_gemm_tf32<<<grid, 256, SMEM>>>(xp, W_ih, b_ih, gxp, NB, H3, HH, 0);
        k_gemm_tf32<<<grid, 256, SMEM>>>(hidden, W_hh, b_hh, ghp, NB, H3, HH, 0);
    }
    // 8. GRU gates -> h_new
    k_gru<<<(NB * HH + 255) / 256, 256>>>(hidden, h_new);

    // 9. logits = h_new @ out_W^T + out_b  [tf32 tensor cores, the big one]
    {
        dim3 grid(OO / 128, NB / 128);
        k_gemm_tf32<<<grid, 256, SMEM>>>(h_new, out_W, out_b, out, NB, OO, HH, 0);
    }
    // 10. log-softmax in place
    k_log_softmax<<<NB, 256>>>(out);
}

// round 3
// speedup vs baseline: 4.3119x; 1.3149x over previous
#include <cuda_runtime.h>
#include <cuda_bf16.h>
#include <math.h>
#include <stdint.h>

// Problem dims
#define NB   1024
#define LL   128
#define HH   512
#define OO   32000
#define H2   1024   // 2H
#define H3   1536   // 3H

#define PAD 36      // smem row stride in floats; LDSM conflict-free (36 mod 32 = 4)

// ---------------- scratch (device globals; no allocation allowed) -----------
__device__ float g_cat[NB * H2];
__device__ float g_x  [NB * HH];
__device__ float g_gx [NB * H3];
__device__ float g_gh [NB * H3];
__device__ float g_rowsum[NB];

// ---------------- PTX helpers ------------------------------------------------
__device__ __forceinline__ void cpasync16(void* s, const void* g)
{
    uint32_t sa = (uint32_t)__cvta_generic_to_shared(s);
    asm volatile("cp.async.cg.shared.global [%0], [%1], 16;\n" :: "r"(sa), "l"(g));
}
__device__ __forceinline__ void cp_commit() { asm volatile("cp.async.commit_group;\n"); }
__device__ __forceinline__ void cp_wait1()  { asm volatile("cp.async.wait_group 1;\n"); }

__device__ __forceinline__ void ldsm_x4(uint32_t* r, uint32_t addr)
{
    asm volatile("ldmatrix.sync.aligned.m8n8.x4.shared.b16 {%0,%1,%2,%3}, [%4];\n"
                 : "=r"(r[0]), "=r"(r[1]), "=r"(r[2]), "=r"(r[3]) : "r"(addr));
}
__device__ __forceinline__ void ldsm_x2(uint32_t* r, uint32_t addr)
{
    asm volatile("ldmatrix.sync.aligned.m8n8.x2.shared.b16 {%0,%1}, [%2];\n"
                 : "=r"(r[0]), "=r"(r[1]) : "r"(addr));
}

__device__ __forceinline__ void mma_tf32(float* d, const uint32_t* a, const uint32_t* b)
{
    asm volatile(
        "mma.sync.aligned.m16n8k8.row.col.f32.tf32.tf32.f32 "
        "{%0,%1,%2,%3}, {%4,%5,%6,%7}, {%8,%9}, {%0,%1,%2,%3};\n"
        : "+f"(d[0]), "+f"(d[1]), "+f"(d[2]), "+f"(d[3])
        : "r"(a[0]), "r"(a[1]), "r"(a[2]), "r"(a[3]), "r"(b[0]), "r"(b[1]));
}

// ---------------- tf32 tensor-core GEMM (LDSM + 3-stage cp.async) -----------
// C[M,Nd] = A[M,K] @ W[Nd,K]^T + bias.  BM=BN=128, BK=32, 256 thr (8 warps 2x4).
// mode: 0 = plain, 1 = relu, 2 = also accumulate sum(exp(v)) per row into rowsum.
#define STAGE_F (2 * 128 * PAD)        // floats per stage (A tile + B tile)

__global__ __launch_bounds__(256, 2)
void k_gemm_tf32(const float* __restrict__ A, const float* __restrict__ W,
                 const float* __restrict__ bias, float* __restrict__ C,
                 float* __restrict__ rowsum,
                 int M, int Nd, int K, int mode)
{
    extern __shared__ float sm[];

    const int bm   = blockIdx.y * 128;
    const int bn   = blockIdx.x * 128;
    const int tid  = threadIdx.x;
    const int warp = tid >> 5;
    const int lane = tid & 31;
    const int gid  = lane >> 2;
    const int tig  = lane & 3;
    const int wm   = (warp >> 2) * 64;
    const int wn   = (warp & 3) * 32;

    // per-thread LDSM source offsets (floats), within a stage's A / B tile
    const int arow = wm + ((lane >> 3) & 1) * 8 + (lane & 7);   // + mt*16
    const int acol = (lane >> 4) * 4;                           // + kk*8
    const int brow = wn + (lane & 7);                           // + nt*8
    const int bcol = ((lane >> 3) & 1) * 4;                     // + kk*8

    const uint32_t smem_u = (uint32_t)__cvta_generic_to_shared(sm);

    float acc[4][4][4];
    #pragma unroll
    for (int i = 0; i < 4; i++)
        #pragma unroll
        for (int j = 0; j < 4; j++)
            #pragma unroll
            for (int r = 0; r < 4; r++) acc[i][j][r] = 0.f;

    const float* Ag = A + (size_t)bm * K;
    const float* Wg = W + (size_t)bn * K;
    const int nIter = K >> 5;

    auto load_tiles = [&](int it, int stg) {
        const float* a_src = Ag + it * 32;
        const float* w_src = Wg + it * 32;
        float* a_dst = sm + stg * STAGE_F;
        float* w_dst = a_dst + 128 * PAD;
        #pragma unroll
        for (int i = 0; i < 4; i++) {
            int f = tid + i * 256;
            int r = f >> 3;
            int c = (f & 7) * 4;
            cpasync16(&a_dst[r * PAD + c], a_src + (size_t)r * K + c);
        }
        #pragma unroll
        for (int i = 0; i < 4; i++) {
            int f = tid + i * 256;
            int r = f >> 3;
            int c = (f & 7) * 4;
            cpasync16(&w_dst[r * PAD + c], w_src + (size_t)r * K + c);
        }
    };

    load_tiles(0, 0); cp_commit();
    load_tiles(1, 1); cp_commit();

    int stg = 0;
    for (int it = 0; it < nIter; ++it) {
        cp_wait1();
        __syncthreads();

        if (it + 2 < nIter) load_tiles(it + 2, (stg + 2) % 3);
        cp_commit();

        const uint32_t aBase = smem_u + (stg * STAGE_F) * 4u;
        const uint32_t bBase = smem_u + (stg * STAGE_F + 128 * PAD) * 4u;

        #pragma unroll
        for (int kk = 0; kk < 4; kk++) {
            uint32_t af[4][4], bf[4][2];
            #pragma unroll
            for (int mt = 0; mt < 4; mt++)
                ldsm_x4(af[mt], aBase + (((arow + mt * 16) * PAD) + kk * 8 + acol) * 4u);
            #pragma unroll
            for (int nt = 0; nt < 4; nt++)
                ldsm_x2(bf[nt], bBase + (((brow + nt * 8) * PAD) + kk * 8 + bcol) * 4u);
            #pragma unroll
            for (int mt = 0; mt < 4; mt++)
                #pragma unroll
                for (int nt = 0; nt < 4; nt++)
                    mma_tf32(acc[mt][nt], af[mt], bf[nt]);
        }
        stg = (stg + 1) % 3;
    }

    // epilogue
    #pragma unroll
    for (int mt = 0; mt < 4; mt++) {
        int r0 = bm + wm + mt * 16 + gid;
        float sum_lo = 0.f, sum_hi = 0.f;
        #pragma unroll
        for (int nt = 0; nt < 4; nt++) {
            int c0 = bn + wn + nt * 8 + tig * 2;
            float b0v = bias[c0], b1v = bias[c0 + 1];
            float v0 = acc[mt][nt][0] + b0v;
            float v1 = acc[mt][nt][1] + b1v;
            float v2 = acc[mt][nt][2] + b0v;
            float v3 = acc[mt][nt][3] + b1v;
            if (mode == 1) {
                v0 = fmaxf(v0, 0.f); v1 = fmaxf(v1, 0.f);
                v2 = fmaxf(v2, 0.f); v3 = fmaxf(v3, 0.f);
            } else if (mode == 2) {
                sum_lo += __expf(v0) + __expf(v1);
                sum_hi += __expf(v2) + __expf(v3);
            }
            *(float2*)&C[(size_t)(r0    ) * Nd + c0] = make_float2(v0, v1);
            *(float2*)&C[(size_t)(r0 + 8) * Nd + c0] = make_float2(v2, v3);
        }
        if (mode == 2) {
            // reduce across the 4 tig lanes (same row), then one atomic per row
            sum_lo += __shfl_xor_sync(0xffffffff, sum_lo, 1);
            sum_lo += __shfl_xor_sync(0xffffffff, sum_lo, 2);
            sum_hi += __shfl_xor_sync(0xffffffff, sum_hi, 1);
            sum_hi += __shfl_xor_sync(0xffffffff, sum_hi, 2);
            if (tig == 0) {
                atomicAdd(&rowsum[r0],     sum_lo);
                atomicAdd(&rowsum[r0 + 8], sum_hi);
            }
        }
    }
}

// ---------------- K1: build cat = [emb[id] | hidden] ------------------------
__global__ void k_build_cat(const int* __restrict__ ids,
                            const float* __restrict__ hidden,
                            const float* __restrict__ emb)
{
    int n = blockIdx.x;
    int id = ids[n];
    const float4* e = (const float4*)(emb + (size_t)id * HH);
    const float4* h = (const float4*)(hidden + (size_t)n * HH);
    float4* c = (float4*)(g_cat + (size_t)n * H2);
    int i = threadIdx.x;                  // 128 threads, HH/4 = 128
    c[i]       = e[i];
    c[128 + i] = h[i];
}

// ---------------- zero rowsum -------------------------------------------------
__global__ void k_zero_rowsum()
{
    g_rowsum[threadIdx.x] = 0.f;          // 1024 threads
}

// ---------------- K3: softmax over L=128 (in place) -------------------------
__global__ void k_softmax128(float* __restrict__ x)
{
    __shared__ float red[128];
    int n = blockIdx.x;
    int t = threadIdx.x;
    float* row = x + (size_t)n * LL;
    float v = row[t];

    red[t] = v; __syncthreads();
    for (int s = 64; s > 0; s >>= 1) {
        if (t < s) red[t] = fmaxf(red[t], red[t + s]);
        __syncthreads();
    }
    float m = red[0]; __syncthreads();

    float e = expf(v - m);
    red[t] = e; __syncthreads();
    for (int s = 64; s > 0; s >>= 1) {
        if (t < s) red[t] += red[t + s];
        __syncthreads();
    }
    float sum = red[0];
    row[t] = e / sum;
}

// ---------------- K4: attn_applied = einsum (fused mask), float4 ------------
__global__ void k_attn_apply(const float* __restrict__ eo,
                             const float* __restrict__ mask,
                             const float* __restrict__ w)
{
    __shared__ float ws[LL];
    int n = blockIdx.x;
    int t = threadIdx.x;                  // 128 threads
    ws[t] = w[(size_t)n * LL + t];
    __syncthreads();

    const float4* e4 = (const float4*)(eo   + (size_t)n * LL * HH) + t;
    const float4* m4 = (const float4*)(mask + (size_t)n * LL * HH) + t;

    float4 acc = make_float4(0.f, 0.f, 0.f, 0.f);
    #pragma unroll 4
    for (int l = 0; l < LL; l++) {
        float4 e = e4[(size_t)l * 128];
        float4 m = m4[(size_t)l * 128];
        float  wv = ws[l];
        acc.x = fmaf(wv, e.x * m.x, acc.x);
        acc.y = fmaf(wv, e.y * m.y, acc.y);
        acc.z = fmaf(wv, e.z * m.z, acc.z);
        acc.w = fmaf(wv, e.w * m.w, acc.w);
    }
    ((float4*)(g_cat + (size_t)n * H2 + HH))[t] = acc;
}

// ---------------- K8: GRU gate pointwise -------------------------------------
__global__ void k_gru(const float* __restrict__ hidden,
                      float* __restrict__ h_new)
{
    int idx = blockIdx.x * blockDim.x + threadIdx.x;
    if (idx >= NB * HH) return;
    int n = idx >> 9;
    int h = idx & (HH - 1);
    size_t base = (size_t)n * H3 + h;

    float xr = g_gx[base], xz = g_gx[base + HH], xn = g_gx[base + 2 * HH];
    float hr = g_gh[base], hz = g_gh[base + HH], hn = g_gh[base + 2 * HH];

    float r = 1.f / (1.f + expf(-(xr + hr)));
    float z = 1.f / (1.f + expf(-(xz + hz)));
    float nn = tanhf(xn + r * hn);
    float hv = hidden[idx];
    h_new[idx] = (1.f - z) * nn + z * hv;
}

// ---------------- K10: out -= log(rowsum)  (finalize log-softmax) ------------
__global__ void k_sub_lse(float* __restrict__ x)
{
    int n = blockIdx.x;
    float lse = __logf(g_rowsum[n]);
    float4* row = (float4*)(x + (size_t)n * OO);
    for (int i = threadIdx.x; i < OO / 4; i += blockDim.x) {
        float4 v = row[i];
        v.x -= lse; v.y -= lse; v.z -= lse; v.w -= lse;
        row[i] = v;
    }
}

// ---------------- launch ------------------------------------------------------
extern "C" void kernel_launch(void* const* d_in, const int* in_sizes, int n_in,
                              void* d_out, int out_size)
{
    const int*   ids     = (const int*)  d_in[0];
    const float* hidden  = (const float*)d_in[1];
    const float* eo      = (const float*)d_in[2];
    const float* mask    = (const float*)d_in[3];
    const float* emb     = (const float*)d_in[4];
    const float* attn_W  = (const float*)d_in[5];
    const float* attn_b  = (const float*)d_in[6];
    const float* comb_W  = (const float*)d_in[7];
    const float* comb_b  = (const float*)d_in[8];
    const float* W_ih    = (const float*)d_in[9];
    const float* W_hh    = (const float*)d_in[10];
    const float* b_ih    = (const float*)d_in[11];
    const float* b_hh    = (const float*)d_in[12];
    const float* out_W   = (const float*)d_in[13];
    const float* out_b   = (const float*)d_in[14];

    float* out    = (float*)d_out;                       // [N, O]
    float* h_new  = out + (size_t)NB * OO;               // [N, H]
    float* attn_w = h_new + (size_t)NB * HH;             // [N, L]

    float* catp;  cudaGetSymbolAddress((void**)&catp, g_cat);
    float* xp;    cudaGetSymbolAddress((void**)&xp,   g_x);
    float* gxp;   cudaGetSymbolAddress((void**)&gxp,  g_gx);
    float* ghp;   cudaGetSymbolAddress((void**)&ghp,  g_gh);
    float* rsp;   cudaGetSymbolAddress((void**)&rsp,  g_rowsum);

    const int SMEM = 3 * STAGE_F * sizeof(float);        // 110592 B
    cudaFuncSetAttribute(k_gemm_tf32, cudaFuncAttributeMaxDynamicSharedMemorySize, SMEM);

    // 1. cat = [emb[ids] | hidden]
    k_build_cat<<<NB, 128>>>(ids, hidden, emb);
    k_zero_rowsum<<<1, NB>>>();

    // 2. attn logits -> attn_w  [tf32]
    {
        dim3 grid(LL / 128, NB / 128);
        k_gemm_tf32<<<grid, 256, SMEM>>>(catp, attn_W, attn_b, attn_w, rsp,
                                         NB, LL, H2, 0);
    }
    // 3. softmax over L
    k_softmax128<<<NB, 128>>>(attn_w);

    // 4. attn_applied (fused mask) -> second half of cat
    k_attn_apply<<<NB, 128>>>(eo, mask, attn_w);

    // 5. x = relu(cat2 @ comb_W^T + b)  [tf32]
    {
        dim3 grid(HH / 128, NB / 128);
        k_gemm_tf32<<<grid, 256, SMEM>>>(catp, comb_W, comb_b, xp, rsp,
                                         NB, HH, H2, 1);
    }
    // 6/7. GRU input/hidden GEMMs  [tf32]
    {
        dim3 grid(H3 / 128, NB / 128);
        k_gemm_tf32<<<grid, 256, SMEM>>>(xp, W_ih, b_ih, gxp, rsp, NB, H3, HH, 0);
        k_gemm_tf32<<<grid, 256, SMEM>>>(hidden, W_hh, b_hh, ghp, rsp, NB, H3, HH, 0);
    }
    // 8. GRU gates -> h_new
    k_gru<<<(NB * HH + 255) / 256, 256>>>(hidden, h_new);

    // 9. logits + fused exp-sum  [tf32]
    {
        dim3 grid(OO / 128, NB / 128);
        k_gemm_tf32<<<grid, 256, SMEM>>>(h_new, out_W, out_b, out, rsp,
                                         NB, OO, HH, 2);
    }
    // 10. finalize log-softmax
    k_sub_lse<<<NB, 256>>>(out);
}

// round 5
// speedup vs baseline: 5.3017x; 1.2296x over previous
#include <cuda_runtime.h>
#include <cuda_fp16.h>
#include <math.h>
#include <stdint.h>

// Problem dims
#define NB   1024
#define LL   128
#define HH   512
#define OO   32000
#define H2   1024   // 2H
#define H3   1536   // 3H

#define HPAD 40     // smem row stride in halfs (32 data + 8 pad) -> ldmatrix conflict-free

// ---------------- scratch (device globals; no allocation allowed) -----------
__device__ __align__(16) __half g_cat_h [NB * H2];   // fp16 [embedded | hidden/attn]
__device__ __align__(16) __half g_x_h   [NB * HH];
__device__ __align__(16) __half g_hid_h [NB * HH];
__device__ __align__(16) __half g_hnew_h[NB * HH];
__device__ float g_gx [NB * H3];
__device__ float g_gh [NB * H3];
__device__ float g_rowsum[NB];

// fp16 weight copies
__device__ __align__(16) __half g_attnW_h[LL * H2];
__device__ __align__(16) __half g_combW_h[HH * H2];
__device__ __align__(16) __half g_Wih_h  [H3 * HH];
__device__ __align__(16) __half g_Whh_h  [H3 * HH];
__device__ __align__(16) __half g_outW_h [OO * HH];

// ---------------- PTX helpers ------------------------------------------------
__device__ __forceinline__ uint32_t smem_u32(const void* p)
{
    return (uint32_t)__cvta_generic_to_shared(p);
}
__device__ __forceinline__ void cpasync16(uint32_t s, const void* g)
{
    asm volatile("cp.async.cg.shared.global [%0], [%1], 16;\n" :: "r"(s), "l"(g));
}
__device__ __forceinline__ void cp_commit() { asm volatile("cp.async.commit_group;\n"); }
__device__ __forceinline__ void cp_wait1()  { asm volatile("cp.async.wait_group 1;\n"); }

__device__ __forceinline__ void ldsm_x4(uint32_t* r, uint32_t addr)
{
    asm volatile("ldmatrix.sync.aligned.m8n8.x4.shared.b16 {%0,%1,%2,%3}, [%4];\n"
                 : "=r"(r[0]), "=r"(r[1]), "=r"(r[2]), "=r"(r[3]) : "r"(addr));
}
__device__ __forceinline__ void ldsm_x2(uint32_t* r, uint32_t addr)
{
    asm volatile("ldmatrix.sync.aligned.m8n8.x2.shared.b16 {%0,%1}, [%2];\n"
                 : "=r"(r[0]), "=r"(r[1]) : "r"(addr));
}
__device__ __forceinline__ void mma_f16(float* d, const uint32_t* a, const uint32_t* b)
{
    asm volatile(
        "mma.sync.aligned.m16n8k16.row.col.f32.f16.f16.f32 "
        "{%0,%1,%2,%3}, {%4,%5,%6,%7}, {%8,%9}, {%0,%1,%2,%3};\n"
        : "+f"(d[0]), "+f"(d[1]), "+f"(d[2]), "+f"(d[3])
        : "r"(a[0]), "r"(a[1]), "r"(a[2]), "r"(a[3]), "r"(b[0]), "r"(b[1]));
}

// =============================================================================
// fp16 HMMA GEMM:  C[M,Nd] = A[M,K] @ W[Nd,K]^T + bias
// BM=BN=128, BK=32, 256 threads (8 warps, 2x4), warp tile 64x32.
// mode 0: fp32 C. mode 1: relu -> fp16 Ch. mode 2: fp32 C + rowsum += sum(exp).
// =============================================================================
#define HSTAGE (2 * 128 * HPAD)      // halfs per stage (A tile + B tile)

__global__ __launch_bounds__(256, 2)
void k_gemm_f16(const __half* __restrict__ A, const __half* __restrict__ W,
                const float* __restrict__ bias,
                float* __restrict__ C, __half* __restrict__ Ch,
                float* __restrict__ rowsum,
                int M, int Nd, int K, int mode)
{
    extern __shared__ __half smh[];

    const int bm   = blockIdx.y * 128;
    const int bn   = blockIdx.x * 128;
    const int tid  = threadIdx.x;
    const int warp = tid >> 5;
    const int lane = tid & 31;
    const int gid  = lane >> 2;
    const int tig  = lane & 3;
    const int wm   = (warp >> 2) * 64;
    const int wn   = (warp & 3) * 32;

    // ldmatrix per-lane offsets (in halfs)
    const int arow = wm + (lane & 15);          // + mt*16
    const int acol = (lane >> 4) * 8;           // + kk*16
    const int brow = wn + (lane & 7);           // + nt*8
    const int bcol = ((lane >> 3) & 1) * 8;     // + kk*16

    const uint32_t smem_b = smem_u32(smh);

    float acc[4][4][4];
    #pragma unroll
    for (int i = 0; i < 4; i++)
        #pragma unroll
        for (int j = 0; j < 4; j++)
            #pragma unroll
            for (int r = 0; r < 4; r++) acc[i][j][r] = 0.f;

    const __half* Ag = A + (size_t)bm * K;
    const __half* Wg = W + (size_t)bn * K;
    const int nIter = K >> 5;

    // tile loader: 128 rows x 32 halfs = 64B/row = 4 x 16B; 512 chunks, 2/thread
    auto load_tiles = [&](int it, int stg) {
        const __half* a_src = Ag + it * 32;
        const __half* w_src = Wg + it * 32;
        uint32_t aBase = smem_b + (stg * HSTAGE) * 2u;
        uint32_t bBase = aBase + 128 * HPAD * 2u;
        #pragma unroll
        for (int j = 0; j < 2; j++) {
            int idx = tid + j * 256;
            int r = idx >> 2;
            int c = (idx & 3) * 8;
            cpasync16(aBase + (r * HPAD + c) * 2u, a_src + (size_t)r * K + c);
        }
        #pragma unroll
        for (int j = 0; j < 2; j++) {
            int idx = tid + j * 256;
            int r = idx >> 2;
            int c = (idx & 3) * 8;
            cpasync16(bBase + (r * HPAD + c) * 2u, w_src + (size_t)r * K + c);
        }
    };

    load_tiles(0, 0); cp_commit();
    load_tiles(1, 1); cp_commit();

    int stg = 0;
    for (int it = 0; it < nIter; ++it) {
        cp_wait1();
        __syncthreads();

        if (it + 2 < nIter) load_tiles(it + 2, (stg + 2) % 3);
        cp_commit();

        const uint32_t aBase = smem_b + (stg * HSTAGE) * 2u;
        const uint32_t bBase = aBase + 128 * HPAD * 2u;

        #pragma unroll
        for (int kk = 0; kk < 2; kk++) {
            uint32_t af[4][4], bf[4][2];
            #pragma unroll
            for (int mt = 0; mt < 4; mt++)
                ldsm_x4(af[mt], aBase + (((arow + mt * 16) * HPAD) + kk * 16 + acol) * 2u);
            #pragma unroll
            for (int nt = 0; nt < 4; nt++)
                ldsm_x2(bf[nt], bBase + (((brow + nt * 8) * HPAD) + kk * 16 + bcol) * 2u);
            #pragma unroll
            for (int mt = 0; mt < 4; mt++)
                #pragma unroll
                for (int nt = 0; nt < 4; nt++)
                    mma_f16(acc[mt][nt], af[mt], bf[nt]);
        }
        stg = (stg + 1) % 3;
    }

    // epilogue
    #pragma unroll
    for (int mt = 0; mt < 4; mt++) {
        int r0 = bm + wm + mt * 16 + gid;
        float sum_lo = 0.f, sum_hi = 0.f;
        #pragma unroll
        for (int nt = 0; nt < 4; nt++) {
            int c0 = bn + wn + nt * 8 + tig * 2;
            float b0v = bias[c0], b1v = bias[c0 + 1];
            float v0 = acc[mt][nt][0] + b0v;
            float v1 = acc[mt][nt][1] + b1v;
            float v2 = acc[mt][nt][2] + b0v;
            float v3 = acc[mt][nt][3] + b1v;
            if (mode == 1) {
                v0 = fmaxf(v0, 0.f); v1 = fmaxf(v1, 0.f);
                v2 = fmaxf(v2, 0.f); v3 = fmaxf(v3, 0.f);
                *(__half2*)&Ch[(size_t)(r0    ) * Nd + c0] = __floats2half2_rn(v0, v1);
                *(__half2*)&Ch[(size_t)(r0 + 8) * Nd + c0] = __floats2half2_rn(v2, v3);
            } else {
                if (mode == 2) {
                    sum_lo += __expf(v0) + __expf(v1);
                    sum_hi += __expf(v2) + __expf(v3);
                }
                *(float2*)&C[(size_t)(r0    ) * Nd + c0] = make_float2(v0, v1);
                *(float2*)&C[(size_t)(r0 + 8) * Nd + c0] = make_float2(v2, v3);
            }
        }
        if (mode == 2) {
            sum_lo += __shfl_xor_sync(0xffffffff, sum_lo, 1);
            sum_lo += __shfl_xor_sync(0xffffffff, sum_lo, 2);
            sum_hi += __shfl_xor_sync(0xffffffff, sum_hi, 1);
            sum_hi += __shfl_xor_sync(0xffffffff, sum_hi, 2);
            if (tig == 0) {
                atomicAdd(&rowsum[r0],     sum_lo);
                atomicAdd(&rowsum[r0 + 8], sum_hi);
            }
        }
    }
}

// ---------------- fp32 -> fp16 conversion -------------------------------------
__global__ void k_f2h(const float4* __restrict__ src, __half2* __restrict__ dst, int n4)
{
    int i = blockIdx.x * blockDim.x + threadIdx.x;
    if (i < n4) {
        float4 v = src[i];
        dst[2 * i]     = __floats2half2_rn(v.x, v.y);
        dst[2 * i + 1] = __floats2half2_rn(v.z, v.w);
    }
}

// ---------------- K1: cat = [emb[id] | hidden] (fp16) + hidden fp16 ----------
__global__ void k_build_cat(const int* __restrict__ ids,
                            const float* __restrict__ hidden,
                            const float* __restrict__ emb)
{
    int n = blockIdx.x;
    int id = ids[n];
    int i = threadIdx.x;                  // 128 threads, 4 elems each
    float4 e = ((const float4*)(emb    + (size_t)id * HH))[i];
    float4 h = ((const float4*)(hidden + (size_t)n  * HH))[i];

    __half2* c = (__half2*)(g_cat_h + (size_t)n * H2);
    c[2 * i]           = __floats2half2_rn(e.x, e.y);
    c[2 * i + 1]       = __floats2half2_rn(e.z, e.w);
    c[256 + 2 * i]     = __floats2half2_rn(h.x, h.y);
    c[256 + 2 * i + 1] = __floats2half2_rn(h.z, h.w);

    __half2* hh = (__half2*)(g_hid_h + (size_t)n * HH);
    hh[2 * i]     = __floats2half2_rn(h.x, h.y);
    hh[2 * i + 1] = __floats2half2_rn(h.z, h.w);
}

__global__ void k_zero_rowsum() { g_rowsum[threadIdx.x] = 0.f; }

// ---------------- K3: softmax over L=128 (in place, fp32) -------------------
__global__ void k_softmax128(float* __restrict__ x)
{
    __shared__ float red[128];
    int n = blockIdx.x;
    int t = threadIdx.x;
    float* row = x + (size_t)n * LL;
    float v = row[t];

    red[t] = v; __syncthreads();
    for (int s = 64; s > 0; s >>= 1) {
        if (t < s) red[t] = fmaxf(red[t], red[t + s]);
        __syncthreads();
    }
    float m = red[0]; __syncthreads();

    float e = expf(v - m);
    red[t] = e; __syncthreads();
    for (int s = 64; s > 0; s >>= 1) {
        if (t < s) red[t] += red[t + s];
        __syncthreads();
    }
    row[t] = e / red[0];
}

// ---------------- K4: attn_applied (fused mask) -> fp16 cat2 ----------------
__global__ void k_attn_apply(const float* __restrict__ eo,
                             const float* __restrict__ mask,
                             const float* __restrict__ w)
{
    __shared__ float ws[LL];
    int n = blockIdx.x;
    int t = threadIdx.x;                  // 128 threads
    ws[t] = w[(size_t)n * LL + t];
    __syncthreads();

    const float4* e4 = (const float4*)(eo   + (size_t)n * LL * HH) + t;
    const float4* m4 = (const float4*)(mask + (size_t)n * LL * HH) + t;

    float4 acc = make_float4(0.f, 0.f, 0.f, 0.f);
    #pragma unroll 4
    for (int l = 0; l < LL; l++) {
        float4 e = e4[(size_t)l * 128];
        float4 m = m4[(size_t)l * 128];
        float  wv = ws[l];
        acc.x = fmaf(wv, e.x * m.x, acc.x);
        acc.y = fmaf(wv, e.y * m.y, acc.y);
        acc.z = fmaf(wv, e.z * m.z, acc.z);
        acc.w = fmaf(wv, e.w * m.w, acc.w);
    }
    __half2* dst = (__half2*)(g_cat_h + (size_t)n * H2 + HH);
    dst[2 * t]     = __floats2half2_rn(acc.x, acc.y);
    dst[2 * t + 1] = __floats2half2_rn(acc.z, acc.w);
}

// ---------------- K8: GRU gates -> h_new fp32 + fp16 -------------------------
__global__ void k_gru(const float* __restrict__ hidden,
                      float* __restrict__ h_new)
{
    int idx = blockIdx.x * blockDim.x + threadIdx.x;
    if (idx >= NB * HH) return;
    int n = idx >> 9;
    int h = idx & (HH - 1);
    size_t base = (size_t)n * H3 + h;

    float xr = g_gx[base], xz = g_gx[base + HH], xn = g_gx[base + 2 * HH];
    float hr = g_gh[base], hz = g_gh[base + HH], hn = g_gh[base + 2 * HH];

    float r = 1.f / (1.f + expf(-(xr + hr)));
    float z = 1.f / (1.f + expf(-(xz + hz)));
    float nn = tanhf(xn + r * hn);
    float hv = (1.f - z) * nn + z * hidden[idx];
    h_new[idx] = hv;
    g_hnew_h[idx] = __float2half_rn(hv);
}

// ---------------- K10: out -= log(rowsum) ------------------------------------
__global__ void k_sub_lse(float* __restrict__ x)
{
    int n = blockIdx.x;
    float lse = __logf(g_rowsum[n]);
    float4* row = (float4*)(x + (size_t)n * OO);
    for (int i = threadIdx.x; i < OO / 4; i += blockDim.x) {
        float4 v = row[i];
        v.x -= lse; v.y -= lse; v.z -= lse; v.w -= lse;
        row[i] = v;
    }
}

// ---------------- launch ------------------------------------------------------
extern "C" void kernel_launch(void* const* d_in, const int* in_sizes, int n_in,
                              void* d_out, int out_size)
{
    const int*   ids     = (const int*)  d_in[0];
    const float* hidden  = (const float*)d_in[1];
    const float* eo      = (const float*)d_in[2];
    const float* mask    = (const float*)d_in[3];
    const float* emb     = (const float*)d_in[4];
    const float* attn_W  = (const float*)d_in[5];
    const float* attn_b  = (const float*)d_in[6];
    const float* comb_W  = (const float*)d_in[7];
    const float* comb_b  = (const float*)d_in[8];
    const float* W_ih    = (const float*)d_in[9];
    const float* W_hh    = (const float*)d_in[10];
    const float* b_ih    = (const float*)d_in[11];
    const float* b_hh    = (const float*)d_in[12];
    const float* out_W   = (const float*)d_in[13];
    const float* out_b   = (const float*)d_in[14];

    float* out    = (float*)d_out;                       // [N, O]
    float* h_new  = out + (size_t)NB * OO;               // [N, H]
    float* attn_w = h_new + (size_t)NB * HH;             // [N, L]

    float* gxp;   cudaGetSymbolAddress((void**)&gxp,  g_gx);
    float* ghp;   cudaGetSymbolAddress((void**)&ghp,  g_gh);
    float* rsp;   cudaGetSymbolAddress((void**)&rsp,  g_rowsum);
    __half *catp, *xp, *hidp, *hnp, *aWp, *cWp, *ihp, *hhp, *oWp;
    cudaGetSymbolAddress((void**)&catp, g_cat_h);
    cudaGetSymbolAddress((void**)&xp,   g_x_h);
    cudaGetSymbolAddress((void**)&hidp, g_hid_h);
    cudaGetSymbolAddress((void**)&hnp,  g_hnew_h);
    cudaGetSymbolAddress((void**)&aWp,  g_attnW_h);
    cudaGetSymbolAddress((void**)&cWp,  g_combW_h);
    cudaGetSymbolAddress((void**)&ihp,  g_Wih_h);
    cudaGetSymbolAddress((void**)&hhp,  g_Whh_h);
    cudaGetSymbolAddress((void**)&oWp,  g_outW_h);

    const int SMEM = 3 * HSTAGE * sizeof(__half);        // 61440 B
    cudaFuncSetAttribute(k_gemm_f16, cudaFuncAttributeMaxDynamicSharedMemorySize, SMEM);

    // 0. weight conversions (graph nodes; independent)
    k_f2h<<<(LL * H2 / 4 + 255) / 256, 256>>>((const float4*)attn_W, (__half2*)aWp, LL * H2 / 4);
    k_f2h<<<(HH * H2 / 4 + 255) / 256, 256>>>((const float4*)comb_W, (__half2*)cWp, HH * H2 / 4);
    k_f2h<<<(H3 * HH / 4 + 255) / 256, 256>>>((const float4*)W_ih, (__half2*)ihp, H3 * HH / 4);
    k_f2h<<<(H3 * HH / 4 + 255) / 256, 256>>>((const float4*)W_hh, (__half2*)hhp, H3 * HH / 4);
    k_f2h<<<((size_t)OO * HH / 4 + 255) / 256, 256>>>((const float4*)out_W, (__half2*)oWp, OO * HH / 4);

    // 1. cat = [emb[ids] | hidden] (fp16) ; hidden fp16
    k_build_cat<<<NB, 128>>>(ids, hidden, emb);
    k_zero_rowsum<<<1, NB>>>();

    // 2. attn logits [fp16 HMMA]
    {
        dim3 grid(LL / 128, NB / 128);
        k_gemm_f16<<<grid, 256, SMEM>>>(catp, aWp, attn_b, attn_w, nullptr, rsp,
                                        NB, LL, H2, 0);
    }
    // 3. softmax over L
    k_softmax128<<<NB, 128>>>(attn_w);
    // 4. attn_applied (fused mask) -> fp16 cat2
    k_attn_apply<<<NB, 128>>>(eo, mask, attn_w);
    // 5. x = relu(cat2 @ comb_W^T + b) -> fp16
    {
        dim3 grid(HH / 128, NB / 128);
        k_gemm_f16<<<grid, 256, SMEM>>>(catp, cWp, comb_b, nullptr, xp, rsp,
                                        NB, HH, H2, 1);
    }
    // 6/7. GRU GEMMs -> fp32 gx, gh
    {
        dim3 grid(H3 / 128, NB / 128);
        k_gemm_f16<<<grid, 256, SMEM>>>(xp,   ihp, b_ih, gxp, nullptr, rsp, NB, H3, HH, 0);
        k_gemm_f16<<<grid, 256, SMEM>>>(hidp, hhp, b_hh, ghp, nullptr, rsp, NB, H3, HH, 0);
    }
    // 8. GRU gates -> h_new (fp32 out + fp16 copy)
    k_gru<<<(NB * HH + 255) / 256, 256>>>(hidden, h_new);

    // 9. big output GEMM + fused exp-sum
    {
        dim3 grid(OO / 128, NB / 128);
        k_gemm_f16<<<grid, 256, SMEM>>>(hnp, oWp, out_b, out, nullptr, rsp,
                                        NB, OO, HH, 2);
    }
    // 10. finalize log-softmax
    k_sub_lse<<<NB, 256>>>(out);
}